// round 3
// baseline (speedup 1.0000x reference)
#include <cuda_runtime.h>

#define GN   128
#define GN2  (GN * GN)
#define GN3  (GN * GN * GN)
#define BIGV 1.0e5f

// Scratch ping-pong buffers (allocation-free rule: __device__ globals).
__device__ float g_bufA[GN3];
__device__ float g_bufB[GN3];

// Process one k-row of 4 cells given its neighbor rows; returns updated float4.
// All lanes of the warp execute this together (shfl-safe).
__device__ __forceinline__ float4 solve_row(
    const float4 uc, const float4 xm4, const float4 xp4,
    const float4 ym4, const float4 yp4,
    const float* __restrict__ frow, int lane)
{
    float left  = __shfl_up_sync(0xffffffffu, uc.w, 1);
    float right = __shfl_down_sync(0xffffffffu, uc.x, 1);
    if (lane == 0)  left  = BIGV;
    if (lane == 31) right = BIGV;

    const float* ucp = (const float*)&uc;
    const float* xmp = (const float*)&xm4;
    const float* xpp = (const float*)&xp4;
    const float* ymp = (const float*)&ym4;
    const float* ypp = (const float*)&yp4;

    float a1[4], a2[4], a3[4];
    bool  act[4];
    bool  anyact = false;

    #pragma unroll
    for (int c = 0; c < 4; ++c) {
        const float zm = (c == 0) ? left  : ucp[c - 1];
        const float zp = (c == 3) ? right : ucp[c + 1];
        const float ax = fminf(xmp[c], xpp[c]);
        const float ay = fminf(ymp[c], ypp[c]);
        const float az = fminf(zm, zp);
        // exact 3-sort via min/max network (matches jnp.sort)
        a1[c] = fminf(ax, fminf(ay, az));
        a3[c] = fmaxf(ax, fmaxf(ay, az));
        a2[c] = fmaxf(fminf(ax, ay), fminf(fmaxf(ax, ay), az));
        // monotone: x >= a1 (fh >= 0.5) so a1 >= u => min(u,x) == u
        act[c] = (a1[c] < ucp[c]);
        anyact |= act[c];
    }

    float4 res = uc;
    float* rp = (float*)&res;

    if (anyact) {
        const float4 f4 = *(const float4*)frow;
        const float* fp = (const float*)&f4;
        #pragma unroll
        for (int c = 0; c < 4; ++c) {
            if (!act[c]) continue;
            const float fh = fp[c];                     // h == 1.0
            const float x1 = a1[c] + fh;
            float x;
            if (x1 <= a2[c]) {
                x = x1;
            } else {
                const float d  = a1[c] - a2[c];
                const float d2 = 2.0f * fh * fh - d * d;
                const float x2 = 0.5f * (a1[c] + a2[c] + sqrtf(fmaxf(d2, 0.0f)));
                if (x2 <= a3[c]) {
                    x = x2;
                } else {
                    const float s  = a1[c] + a2[c] + a3[c];
                    const float q  = a1[c] * a1[c] + a2[c] * a2[c] + a3[c] * a3[c];
                    const float d3 = s * s - 3.0f * (q - fh * fh);
                    x = (s + sqrtf(fmaxf(d3, 0.0f))) / 3.0f;
                }
            }
            rp[c] = fminf(ucp[c], x);
        }
    }
    return res;
}

__global__ void __launch_bounds__(256, 6) eik_step(
    const float* __restrict__ src,
    const float* __restrict__ f,
    float* __restrict__ dst)
{
    const int lane = threadIdx.x;                    // 0..31, k in float4s
    const int j  = blockIdx.y * 8 + threadIdx.y;     // blockDim.y = 8
    const int i0 = blockIdx.z * 2;                   // two i-planes per thread
    const int idx0 = (i0 * GN + j) * GN + lane * 4;
    const int idx1 = idx0 + GN2;

    const float4 big4 = make_float4(BIGV, BIGV, BIGV, BIGV);

    // Front-batched loads: 8 LDG.128 (high MLP)
    const float4 uc0 = *(const float4*)(src + idx0);
    const float4 uc1 = *(const float4*)(src + idx1);
    const float4 xm  = (i0 > 0)       ? *(const float4*)(src + idx0 - GN2) : big4;
    const float4 xp  = (i0 + 2 < GN)  ? *(const float4*)(src + idx1 + GN2) : big4;
    const float4 ym0 = (j > 0)        ? *(const float4*)(src + idx0 - GN)  : big4;
    const float4 yp0 = (j < GN - 1)   ? *(const float4*)(src + idx0 + GN)  : big4;
    const float4 ym1 = (j > 0)        ? *(const float4*)(src + idx1 - GN)  : big4;
    const float4 yp1 = (j < GN - 1)   ? *(const float4*)(src + idx1 + GN)  : big4;

    // Row 0: x-neighbors are (xm, uc1). Row 1: (uc0, xp) — middle plane reused.
    const float4 r0 = solve_row(uc0, xm,  uc1, ym0, yp0, f + idx0, lane);
    const float4 r1 = solve_row(uc1, uc0, xp,  ym1, yp1, f + idx1, lane);

    *(float4*)(dst + idx0) = r0;
    *(float4*)(dst + idx1) = r1;
}

extern "C" void kernel_launch(void* const* d_in, const int* in_sizes, int n_in,
                              void* d_out, int out_size)
{
    const float* u0 = (const float*)d_in[0];
    const float* f  = (const float*)d_in[1];
    float* out      = (float*)d_out;

    float* bufA = nullptr;
    float* bufB = nullptr;
    cudaGetSymbolAddress((void**)&bufA, g_bufA);
    cudaGetSymbolAddress((void**)&bufB, g_bufB);

    const dim3 blk(32, 8, 1);
    const dim3 grd(1, GN / 8, GN / 2);

    const float* src = u0;
    for (int it = 0; it < 128; ++it) {
        float* dst = (it == 127) ? out : ((it & 1) ? bufB : bufA);
        eik_step<<<grd, blk>>>(src, f, dst);
        src = dst;
    }
}

// round 4
// speedup vs baseline: 1.1931x; 1.1931x over previous
#include <cuda_runtime.h>

#define GN   128
#define GN2  (GN * GN)
#define GN3  (GN * GN * GN)
#define BIGV 1.0e5f

// Scratch ping-pong buffers (allocation-free rule: __device__ globals).
__device__ float g_bufA[GN3];
__device__ float g_bufB[GN3];

__global__ void __launch_bounds__(256) eik_step(
    const float* __restrict__ src,
    const float* __restrict__ f,
    float* __restrict__ dst)
{
    const int lane = threadIdx.x;                      // 0..31, covers k in float4s
    const int j = blockIdx.y * 8 + threadIdx.y;
    const int i = blockIdx.z;
    const int idx = (i * GN + j) * GN + lane * 4;

    const float4 big4 = make_float4(BIGV, BIGV, BIGV, BIGV);

    // Front-batched loads (5 src rows + the current dst row for skip-write)
    const float4 uc  = *(const float4*)(src + idx);
    const float4 xm4 = (i > 0)      ? *(const float4*)(src + idx - GN2) : big4;
    const float4 xp4 = (i < GN - 1) ? *(const float4*)(src + idx + GN2) : big4;
    const float4 ym4 = (j > 0)      ? *(const float4*)(src + idx - GN)  : big4;
    const float4 yp4 = (j < GN - 1) ? *(const float4*)(src + idx + GN)  : big4;
    const ulonglong2 oldv = *(const ulonglong2*)(dst + idx);

    // z-edge neighbors across lanes (warp is exactly one k-row)
    float left  = __shfl_up_sync(0xffffffffu, uc.w, 1);
    float right = __shfl_down_sync(0xffffffffu, uc.x, 1);
    if (lane == 0)  left  = BIGV;
    if (lane == 31) right = BIGV;

    const float* ucp = (const float*)&uc;
    const float* xmp = (const float*)&xm4;
    const float* xpp = (const float*)&xp4;
    const float* ymp = (const float*)&ym4;
    const float* ypp = (const float*)&yp4;

    // Cheap activity test: only a1 = min of 6 neighbors is needed.
    // Monotone: x >= a1 (fh >= 0.5) so a1 >= u => min(u,x) == u.
    bool act[4];
    bool anyact = false;
    #pragma unroll
    for (int c = 0; c < 4; ++c) {
        const float zm = (c == 0) ? left  : ucp[c - 1];
        const float zp = (c == 3) ? right : ucp[c + 1];
        const float a1 = fminf(fminf(fminf(xmp[c], xpp[c]), fminf(ymp[c], ypp[c])),
                               fminf(zm, zp));
        act[c] = (a1 < ucp[c]);
        anyact |= act[c];
    }

    float4 res = uc;
    float* rp = (float*)&res;

    if (anyact) {
        const float4 f4 = *(const float4*)(f + idx);
        const float* fp = (const float*)&f4;
        #pragma unroll
        for (int c = 0; c < 4; ++c) {
            if (!act[c]) continue;
            const float zm = (c == 0) ? left  : ucp[c - 1];
            const float zp = (c == 3) ? right : ucp[c + 1];
            const float ax = fminf(xmp[c], xpp[c]);
            const float ay = fminf(ymp[c], ypp[c]);
            const float az = fminf(zm, zp);
            // exact 3-sort via min/max network (matches jnp.sort)
            const float a1 = fminf(ax, fminf(ay, az));
            const float a3 = fmaxf(ax, fmaxf(ay, az));
            const float a2 = fmaxf(fminf(ax, ay), fminf(fmaxf(ax, ay), az));

            const float fh = fp[c];                     // h == 1.0
            const float x1 = a1 + fh;
            float x;
            if (x1 <= a2) {
                x = x1;
            } else {
                const float d  = a1 - a2;
                const float d2 = 2.0f * fh * fh - d * d;
                const float x2 = 0.5f * (a1 + a2 + sqrtf(fmaxf(d2, 0.0f)));
                if (x2 <= a3) {
                    x = x2;
                } else {
                    const float s  = a1 + a2 + a3;
                    const float q  = a1 * a1 + a2 * a2 + a3 * a3;
                    const float d3 = s * s - 3.0f * (q - fh * fh);
                    x = (s + sqrtf(fmaxf(d3, 0.0f))) / 3.0f;
                }
            }
            rp[c] = fminf(ucp[c], x);
        }
    }

    // Skip-write: store only if dst content differs (self-validating — after
    // this kernel dst == res regardless of dst's prior content).
    const ulonglong2 newv = *(const ulonglong2*)&res;
    if (oldv.x != newv.x || oldv.y != newv.y) {
        *(float4*)(dst + idx) = res;
    }
}

extern "C" void kernel_launch(void* const* d_in, const int* in_sizes, int n_in,
                              void* d_out, int out_size)
{
    const float* u0 = (const float*)d_in[0];
    const float* f  = (const float*)d_in[1];
    float* out      = (float*)d_out;

    float* bufA = nullptr;
    float* bufB = nullptr;
    cudaGetSymbolAddress((void**)&bufA, g_bufA);
    cudaGetSymbolAddress((void**)&bufB, g_bufB);

    const dim3 blk(32, 8, 1);
    const dim3 grd(1, GN / 8, GN);

    const float* src = u0;
    for (int it = 0; it < 128; ++it) {
        float* dst = (it == 127) ? out : ((it & 1) ? bufB : bufA);
        eik_step<<<grd, blk>>>(src, f, dst);
        src = dst;
    }
}